// round 1
// baseline (speedup 1.0000x reference)
#include <cuda_runtime.h>
#include <cuda_bf16.h>
#include <math.h>

#define NT 1024      // tokens
#define WD 300
#define PD 25
#define DIN 325      // WD+PD
#define HID 125
#define G4 500       // 4*HID
#define TWOH 250
#define FC 100
#define NN (NT*NT)

// ---------------- scratch (no allocations allowed) ----------------
__device__ float g_x[NT * DIN];
__device__ float g_pre[2 * NT * G4];
__device__ float g_h0[NT * TWOH];
__device__ float g_h1[NT * TWOH];
__device__ float g_A[NT * FC];
__device__ float g_B[NT * FC];
__device__ float g_scores_scratch[NN];
__device__ float g_colloss[NT];

// ---------------- embedding concat ----------------
__global__ void embed_kernel(const float* __restrict__ wv,
                             const int* __restrict__ pidx,
                             const float* __restrict__ pemb) {
    int t = blockIdx.x;
    int tid = threadIdx.x;
    if (tid < WD) {
        g_x[t * DIN + tid] = wv[t * WD + tid];
    } else if (tid < DIN) {
        g_x[t * DIN + tid] = pemb[pidx[t] * PD + (tid - WD)];
    }
}

// ---------------- generic C[m][n] = bias[n] + sum_k A[m,k]*B[n,k] ----------------
__global__ void gemm_tn(const float* __restrict__ A, int lda,
                        const float* __restrict__ B, int ldb,
                        const float* __restrict__ bias,
                        float* __restrict__ C, int ldc,
                        int M, int N, int K) {
    __shared__ float As[32][33];
    __shared__ float Bs[32][33];
    int tx = threadIdx.x, ty = threadIdx.y;
    int bm = blockIdx.y * 32, bn = blockIdx.x * 32;
    float c00 = 0.f, c01 = 0.f, c10 = 0.f, c11 = 0.f;
    for (int k0 = 0; k0 < K; k0 += 32) {
        #pragma unroll
        for (int i = ty; i < 32; i += 16) {
            #pragma unroll
            for (int kk = tx; kk < 32; kk += 16) {
                int m = bm + i, k = k0 + kk;
                As[i][kk] = (m < M && k < K) ? A[m * lda + k] : 0.f;
                int n = bn + i;
                Bs[i][kk] = (n < N && k < K) ? B[n * ldb + k] : 0.f;
            }
        }
        __syncthreads();
        #pragma unroll
        for (int kk = 0; kk < 32; kk++) {
            float a0 = As[ty][kk], a1 = As[ty + 16][kk];
            float b0 = Bs[tx][kk], b1 = Bs[tx + 16][kk];
            c00 = fmaf(a0, b0, c00); c01 = fmaf(a0, b1, c01);
            c10 = fmaf(a1, b0, c10); c11 = fmaf(a1, b1, c11);
        }
        __syncthreads();
    }
    int m0 = bm + ty, m1 = m0 + 16, n0 = bn + tx, n1 = n0 + 16;
    float bv0 = (bias && n0 < N) ? bias[n0] : 0.f;
    float bv1 = (bias && n1 < N) ? bias[n1] : 0.f;
    if (m0 < M && n0 < N) C[m0 * ldc + n0] = c00 + bv0;
    if (m0 < M && n1 < N) C[m0 * ldc + n1] = c01 + bv1;
    if (m1 < M && n0 < N) C[m1 * ldc + n0] = c10 + bv0;
    if (m1 < M && n1 < N) C[m1 * ldc + n1] = c11 + bv1;
}

// ---------------- recurrent LSTM (one CTA per direction) ----------------
// pre: [2][NT][G4] (x@Wih^T + b precomputed), Whh: [2][G4][HID]
// hout: [NT][TWOH], direction writes columns [dir*HID, dir*HID+HID)
#define NREG4 20   // 80 K-values in registers
#define NSM4  12   // 48 K-values (padded, 125->128) in smem

__global__ __launch_bounds__(512, 1) void lstm_kernel(
        const float* __restrict__ pre,
        const float* __restrict__ Whh,
        float* __restrict__ hout) {
    extern __shared__ float smem[];
    float4* wsm4 = (float4*)smem;                  // [NSM4][512]
    float* h_sh = smem + NSM4 * 512 * 4;           // [128] (padded h)
    float* g_sh = h_sh + 128;                      // [512]

    int dir = blockIdx.x;
    const float* preD = pre + (size_t)dir * NT * G4;
    const float* W = Whh + (size_t)dir * G4 * HID;
    int o = threadIdx.x;

    // stage weights: k<80 in regs, k 80..127 (zero padded) in smem transposed
    float4 wr[NREG4];
    #pragma unroll
    for (int q = 0; q < NREG4; q++) {
        float4 v = make_float4(0.f, 0.f, 0.f, 0.f);
        if (o < G4) {
            const float* row = W + o * HID + 4 * q;
            v.x = row[0]; v.y = row[1]; v.z = row[2]; v.w = row[3];
        }
        wr[q] = v;
    }
    #pragma unroll
    for (int q = 0; q < NSM4; q++) {
        float4 v = make_float4(0.f, 0.f, 0.f, 0.f);
        if (o < G4) {
            int k = 80 + 4 * q;
            v.x = W[o * HID + k];
            if (k + 1 < HID) v.y = W[o * HID + k + 1];
            if (k + 2 < HID) v.z = W[o * HID + k + 2];
            if (k + 3 < HID) v.w = W[o * HID + k + 3];
        }
        wsm4[q * 512 + o] = v;
    }
    if (o < 128) h_sh[o] = 0.f;
    float c = 0.f;
    int gate = o / HID;
    bool is_tanh_gate = (gate == 2);
    __syncthreads();

    int t0 = dir ? (NT - 1) : 0;
    float pre_cur = (o < G4) ? preD[(size_t)t0 * G4 + o] : 0.f;

    for (int s = 0; s < NT; s++) {
        int t = dir ? (NT - 1 - s) : s;
        int tn = dir ? (t - 1) : (t + 1);
        float pre_nxt = (s + 1 < NT && o < G4) ? preD[(size_t)tn * G4 + o] : 0.f;

        float a0 = pre_cur, a1 = 0.f, a2 = 0.f, a3 = 0.f;
        const float4* h4 = (const float4*)h_sh;
        #pragma unroll
        for (int q = 0; q < NREG4; q++) {
            float4 hv = h4[q];
            a0 = fmaf(wr[q].x, hv.x, a0);
            a1 = fmaf(wr[q].y, hv.y, a1);
            a2 = fmaf(wr[q].z, hv.z, a2);
            a3 = fmaf(wr[q].w, hv.w, a3);
        }
        #pragma unroll
        for (int q = 0; q < NSM4; q++) {
            float4 hv = h4[NREG4 + q];
            float4 wv = wsm4[q * 512 + o];
            a0 = fmaf(wv.x, hv.x, a0);
            a1 = fmaf(wv.y, hv.y, a1);
            a2 = fmaf(wv.z, hv.z, a2);
            a3 = fmaf(wv.w, hv.w, a3);
        }
        float g = (a0 + a1) + (a2 + a3);
        float act;
        if (is_tanh_gate) act = tanhf(g);
        else act = 1.f / (1.f + __expf(-g));
        if (o < G4) g_sh[o] = act;
        __syncthreads();
        if (o < HID) {
            float ig = g_sh[o];
            float fg = g_sh[HID + o];
            float gg = g_sh[2 * HID + o];
            float og = g_sh[3 * HID + o];
            c = fmaf(fg, c, ig * gg);
            float h = og * tanhf(c);
            h_sh[o] = h;
            hout[(size_t)t * TWOH + dir * HID + o] = h;
        }
        __syncthreads();
        pre_cur = pre_nxt;
    }
}

// ---------------- pair scores ----------------
__device__ __forceinline__ float fast_tanh(float z) {
    z = fminf(fmaxf(z, -15.f), 15.f);
    float e = __expf(2.f * z);
    return __fdividef(e - 1.f, e + 1.f);
}

__global__ __launch_bounds__(256) void pair_kernel(
        const float* __restrict__ Ac,   // [NT][FC], fc1_b folded in
        const float* __restrict__ Bc,   // [NT][FC]
        const float* __restrict__ w2,   // [FC]
        const float* __restrict__ b2,   // [1]
        float* __restrict__ S) {
    __shared__ float Asm[32][101];
    __shared__ float Bsm[32][101];
    __shared__ float wsm[FC];
    int tx = threadIdx.x, ty = threadIdx.y;   // (32,8)
    int tid = ty * 32 + tx;
    int i0 = blockIdx.y * 32, j0 = blockIdx.x * 32;
    for (int idx = tid; idx < 32 * FC; idx += 256) {
        int r = idx / FC, f = idx - FC * r;
        Asm[r][f] = Ac[(i0 + r) * FC + f];
        Bsm[r][f] = Bc[(j0 + r) * FC + f];
    }
    if (tid < FC) wsm[tid] = w2[tid];
    __syncthreads();
    float fb = b2[0];
    float acc0 = 0.f, acc1 = 0.f, acc2 = 0.f, acc3 = 0.f;
    #pragma unroll 4
    for (int f = 0; f < FC; f++) {
        float b = Bsm[tx][f];
        float wv = wsm[f];
        acc0 = fmaf(fast_tanh(Asm[ty][f] + b), wv, acc0);
        acc1 = fmaf(fast_tanh(Asm[ty + 8][f] + b), wv, acc1);
        acc2 = fmaf(fast_tanh(Asm[ty + 16][f] + b), wv, acc2);
        acc3 = fmaf(fast_tanh(Asm[ty + 24][f] + b), wv, acc3);
    }
    int j = j0 + tx;
    float v[4] = {acc0 + fb, acc1 + fb, acc2 + fb, acc3 + fb};
    #pragma unroll
    for (int s = 0; s < 4; s++) {
        int i = i0 + ty + 8 * s;
        float out = (i == j || j == 0) ? 0.f : v[s];
        S[(size_t)i * NT + j] = out;
    }
}

// ---------------- per-column logsumexp + NLL ----------------
__global__ void colloss_kernel(const float* __restrict__ S,
                               const int* __restrict__ parents) {
    int tx = threadIdx.x, ty = threadIdx.y;  // (32,8)
    int j = blockIdx.x * 32 + tx;
    float m = -1e30f, ss = 0.f;
    for (int r = ty; r < NT; r += 8) {
        float x = S[(size_t)r * NT + j];
        if (x > m) { ss = ss * __expf(m - x) + 1.f; m = x; }
        else       { ss += __expf(x - m); }
    }
    __shared__ float Mv[8][33], Sv[8][33];
    Mv[ty][tx] = m; Sv[ty][tx] = ss;
    __syncthreads();
    if (ty == 0) {
        float M = Mv[0][tx], SS = Sv[0][tx];
        #pragma unroll
        for (int r = 1; r < 8; r++) {
            float m2 = Mv[r][tx], s2 = Sv[r][tx];
            if (m2 > M) { SS = SS * __expf(M - m2) + s2; M = m2; }
            else        { SS += s2 * __expf(m2 - M); }
        }
        int p = parents[j];
        g_colloss[j] = (M + logf(SS)) - S[(size_t)p * NT + j];
    }
}

__global__ void loss_kernel(float* __restrict__ lossptr) {
    __shared__ float sm[256];
    int tid = threadIdx.x;
    float s = 0.f;
    for (int i = tid; i < NT; i += 256) s += g_colloss[i];
    sm[tid] = s;
    __syncthreads();
    for (int off = 128; off > 0; off >>= 1) {
        if (tid < off) sm[tid] += sm[tid + off];
        __syncthreads();
    }
    if (tid == 0) *lossptr = sm[0] / (float)NT;
}

// ---------------- launch ----------------
extern "C" void kernel_launch(void* const* d_in, const int* in_sizes, int n_in,
                              void* d_out, int out_size) {
    (void)in_sizes; (void)n_in;
    const float* word_vecs = (const float*)d_in[0];
    const int*   pos_idx   = (const int*)d_in[1];
    const int*   parents   = (const int*)d_in[2];
    const float* pos_emb   = (const float*)d_in[3];
    const float* Wih0      = (const float*)d_in[4];
    const float* Whh0      = (const float*)d_in[5];
    const float* b0        = (const float*)d_in[6];
    const float* Wih1      = (const float*)d_in[7];
    const float* Whh1      = (const float*)d_in[8];
    const float* b1        = (const float*)d_in[9];
    const float* fc1_W     = (const float*)d_in[10];
    const float* fc1_b     = (const float*)d_in[11];
    const float* fc2_W     = (const float*)d_in[12];
    const float* fc2_b     = (const float*)d_in[13];
    float* out = (float*)d_out;

    // scratch addresses
    float *px, *ppre, *ph0, *ph1, *pA, *pB, *pscratch;
    cudaGetSymbolAddress((void**)&px, g_x);
    cudaGetSymbolAddress((void**)&ppre, g_pre);
    cudaGetSymbolAddress((void**)&ph0, g_h0);
    cudaGetSymbolAddress((void**)&ph1, g_h1);
    cudaGetSymbolAddress((void**)&pA, g_A);
    cudaGetSymbolAddress((void**)&pB, g_B);
    cudaGetSymbolAddress((void**)&pscratch, g_scores_scratch);

    // output layout: tuple (loss, scores_mat) flattened; be robust to variants
    float* scores;
    float* lossp = nullptr;
    if (out_size >= NN) {
        scores = out + (out_size - NN);
        if (out_size > NN) lossp = out;
    } else {
        scores = pscratch;
        lossp = out;
    }

    const int lstm_smem = NSM4 * 512 * 16 + 128 * 4 + 512 * 4;
    cudaFuncSetAttribute(lstm_kernel, cudaFuncAttributeMaxDynamicSharedMemorySize,
                         lstm_smem);

    // 1) embeddings
    embed_kernel<<<NT, 352>>>(word_vecs, pos_idx, pos_emb);

    // 2) pre0[d] = x @ Wih0[d]^T + b0[d]
    {
        dim3 g((G4 + 31) / 32, (NT + 31) / 32), b(16, 16);
        for (int d = 0; d < 2; d++)
            gemm_tn<<<g, b>>>(px, DIN, Wih0 + (size_t)d * G4 * DIN, DIN,
                              b0 + d * G4, ppre + (size_t)d * NT * G4, G4,
                              NT, G4, DIN);
    }
    // 3) layer0 recurrence (fwd+bwd in parallel CTAs)
    lstm_kernel<<<2, 512, lstm_smem>>>(ppre, Whh0, ph0);

    // 4) pre1[d] = h0 @ Wih1[d]^T + b1[d]
    {
        dim3 g((G4 + 31) / 32, (NT + 31) / 32), b(16, 16);
        for (int d = 0; d < 2; d++)
            gemm_tn<<<g, b>>>(ph0, TWOH, Wih1 + (size_t)d * G4 * TWOH, TWOH,
                              b1 + d * G4, ppre + (size_t)d * NT * G4, G4,
                              NT, G4, TWOH);
    }
    // 5) layer1 recurrence
    lstm_kernel<<<2, 512, lstm_smem>>>(ppre, Whh1, ph1);

    // 6) A = h1 @ fc1_W[:, :250]^T + fc1_b ; B = h1 @ fc1_W[:, 250:]^T
    {
        dim3 g((FC + 31) / 32, (NT + 31) / 32), b(16, 16);
        gemm_tn<<<g, b>>>(ph1, TWOH, fc1_W, 2 * TWOH, fc1_b, pA, FC, NT, FC, TWOH);
        gemm_tn<<<g, b>>>(ph1, TWOH, fc1_W + TWOH, 2 * TWOH, nullptr, pB, FC, NT, FC, TWOH);
    }

    // 7) pairwise scores (masked) straight into output location
    {
        dim3 g(NT / 32, NT / 32), b(32, 8);
        pair_kernel<<<g, b>>>(pA, pB, fc2_W, fc2_b, scores);
    }

    // 8) loss
    if (lossp) {
        dim3 b(32, 8);
        colloss_kernel<<<NT / 32, b>>>(scores, parents);
        loss_kernel<<<1, 256>>>(lossp);
    }
}